// round 3
// baseline (speedup 1.0000x reference)
#include <cuda_runtime.h>
#include <cuda_bf16.h>

#define N_NODES 50000
#define N_EDGES 800000
#define C1 128
#define C2 256
#define NB_N ((N_NODES + 255) / 256)   // 196
#define NB_E ((N_EDGES + 255) / 256)   // 3125

// ---------------- device scratch (static, no allocation) ----------------
__device__ int      g_is64;
__device__ int      g_degi[N_NODES];
__device__ float    g_dinv[N_NODES];
__device__ int      g_rowoff[N_NODES + 1];
__device__ int      g_cursor[N_NODES];
__device__ int      g_partial[256];
__device__ int      g_csr_src[N_EDGES];
__device__ float    g_csr_nrm[N_EDGES];
__device__ float    g_h1[(long long)N_NODES * C1];
__device__ float    g_agg1[(long long)N_NODES * C1];
__device__ float    g_h2[(long long)N_NODES * C2];
__device__ float    g_logits[N_NODES];
__device__ float    g_pw[N_NODES];
__device__ unsigned g_maxkey;
__device__ float    g_sumexp;

// ---------------- helpers ----------------
__device__ __forceinline__ int edge_idx(const void* ei, long long i, int is64) {
    if (is64) return (int)((const long long*)ei)[i];
    return ((const int*)ei)[i];
}
__device__ __forceinline__ unsigned enc_f(float f) {
    unsigned u = __float_as_uint(f);
    return (u & 0x80000000u) ? ~u : (u | 0x80000000u);
}
__device__ __forceinline__ float dec_f(unsigned k) {
    unsigned u = (k & 0x80000000u) ? (k ^ 0x80000000u) : ~k;
    return __uint_as_float(u);
}

// ---------------- preprocessing ----------------
__global__ void k_sniff(const void* ei) {
    // Decide whether edge_index is int64 or int32 (JAX x64 config ambiguity).
    // If the first 64 entries, read as int64, all lie in [0, N_NODES), the
    // buffer is int64 (false positive prob ~ (5e4/2^63)-ish: negligible).
    const long long* p = (const long long*)ei;
    int ok = 1;
    for (int i = 0; i < 64; i++) {
        long long v = p[i];
        if (v < 0 || v >= N_NODES) { ok = 0; break; }
    }
    g_is64 = ok;
}

__global__ void k_init() {
    int i = blockIdx.x * blockDim.x + threadIdx.x;
    if (i < N_NODES) g_degi[i] = 0;
    if (i == 0) { g_maxkey = 0u; g_sumexp = 0.f; }
}

__global__ void k_count(const void* ei) {
    int e = blockIdx.x * blockDim.x + threadIdx.x;
    if (e >= N_EDGES) return;
    int d = edge_idx(ei, (long long)N_EDGES + e, g_is64);
    atomicAdd(&g_degi[d], 1);
}

__global__ void k_dinv() {
    int i = blockIdx.x * blockDim.x + threadIdx.x;
    if (i < N_NODES) g_dinv[i] = rsqrtf((float)(g_degi[i] + 1)); // +1 self loop
}

__global__ void k_scan1() {
    __shared__ int sh[256];
    int t = threadIdx.x;
    int i = blockIdx.x * 256 + t;
    int v = (i < N_NODES) ? g_degi[i] : 0;
    sh[t] = v;
    __syncthreads();
    for (int off = 1; off < 256; off <<= 1) {
        int add = (t >= off) ? sh[t - off] : 0;
        __syncthreads();
        sh[t] += add;
        __syncthreads();
    }
    if (i < N_NODES) g_rowoff[i + 1] = sh[t];
    if (t == 255) g_partial[blockIdx.x] = sh[255];
}

__global__ void k_scan2() {
    __shared__ int sh[256];
    int t = threadIdx.x;
    int v = (t < NB_N) ? g_partial[t] : 0;
    sh[t] = v;
    __syncthreads();
    for (int off = 1; off < 256; off <<= 1) {
        int add = (t >= off) ? sh[t - off] : 0;
        __syncthreads();
        sh[t] += add;
        __syncthreads();
    }
    g_partial[t] = sh[t] - v; // exclusive
}

__global__ void k_scan3() {
    int i = blockIdx.x * blockDim.x + threadIdx.x;
    if (i < N_NODES) g_rowoff[i + 1] += g_partial[i >> 8];
    if (i == 0) g_rowoff[0] = 0;
}

__global__ void k_cursor() {
    int i = blockIdx.x * blockDim.x + threadIdx.x;
    if (i < N_NODES) g_cursor[i] = g_rowoff[i];
}

__global__ void k_scatter(const void* ei) {
    int e = blockIdx.x * blockDim.x + threadIdx.x;
    if (e >= N_EDGES) return;
    int is64 = g_is64;
    int s = edge_idx(ei, e, is64);
    int d = edge_idx(ei, (long long)N_EDGES + e, is64);
    int pos = atomicAdd(&g_cursor[d], 1);
    g_csr_src[pos] = s;
    g_csr_nrm[pos] = g_dinv[s] * g_dinv[d];
}

// ---------------- dense GEMM: out[N,C] = X[N,128] @ W[128,C] ----------------
// Block tile 32 rows x 64 cols. W column-tile (128x64, 32KB) + X tile stored
// transposed (Xt[128][32], 16KB) = 49152B static smem exactly (no opt-in).
// 256 threads = 16(tx, 4 cols each) x 16(ty); each thread does rows ty, ty+16.
// Xt[k][r] layout: per-k X reads hit bank==ty -> conflict-free without pad.
template <int C>
__global__ void __launch_bounds__(256) k_gemm(const float* __restrict__ X,
                                              const float* __restrict__ W,
                                              float* __restrict__ out) {
    __shared__ float Ws[128 * 64];   // Ws4[k*16+t] = W[k][col0 + 4t .. 4t+3]
    __shared__ float Xt[128 * 32];   // Xt[k*32+r] = X[row0+r][k]

    const int col0 = blockIdx.y * 64;
    float4* Ws4 = (float4*)Ws;

    for (int i = threadIdx.x; i < 128 * 16; i += 256) {
        int k = i >> 4, t = i & 15;
        Ws4[i] = ((const float4*)(W + (long long)k * C + col0))[t];
    }
    __syncthreads();

    const int tx = threadIdx.x & 15;
    const int ty = threadIdx.x >> 4;
    const int ntiles = (N_NODES + 31) / 32;  // 1563 (last tile partial: 16 rows)

    for (int tile = blockIdx.x; tile < ntiles; tile += gridDim.x) {
        int row0 = tile * 32;
        for (int i = threadIdx.x; i < 32 * 128; i += 256) {
            int r = i & 31, c = i >> 5;
            int row = row0 + r;
            Xt[c * 32 + r] = (row < N_NODES) ? X[(long long)row * 128 + c] : 0.f;
        }
        __syncthreads();

        float4 a0 = make_float4(0.f, 0.f, 0.f, 0.f);
        float4 a1 = make_float4(0.f, 0.f, 0.f, 0.f);

#pragma unroll 4
        for (int k = 0; k < 128; k++) {
            float4 w = Ws4[k * 16 + tx];
            float x0 = Xt[k * 32 + ty];
            float x1 = Xt[k * 32 + ty + 16];
            a0.x += x0 * w.x; a0.y += x0 * w.y; a0.z += x0 * w.z; a0.w += x0 * w.w;
            a1.x += x1 * w.x; a1.y += x1 * w.y; a1.z += x1 * w.z; a1.w += x1 * w.w;
        }

        int r0 = row0 + ty;
        int r1 = row0 + ty + 16;
        if (r0 < N_NODES)
            *(float4*)(out + (long long)r0 * C + col0 + tx * 4) = a0;
        if (r1 < N_NODES)
            *(float4*)(out + (long long)r1 * C + col0 + tx * 4) = a1;
        __syncthreads();
    }
}

// ---------------- aggregation: warp per node, gather over CSR ----------------
// out[d] = relu( bias + dinv[d]^2 * h[d] + sum_edges nrm * h[src] )
template <int C>
__global__ void k_agg(const float* __restrict__ h,
                      const float* __restrict__ bias,
                      float* __restrict__ out) {
    constexpr int NV4 = C / 4;
    int d = (blockIdx.x * blockDim.x + threadIdx.x) >> 5;
    int lane = threadIdx.x & 31;
    if (d >= N_NODES) return;

    const float4* h4 = (const float4*)h;
    const float4* b4 = (const float4*)bias;

    float di = g_dinv[d];
    float sl = di * di;

    float4 a0 = b4[lane];
    float4 v0 = h4[(long long)d * NV4 + lane];
    a0.x += sl * v0.x; a0.y += sl * v0.y; a0.z += sl * v0.z; a0.w += sl * v0.w;
    float4 a1;
    if constexpr (C == 256) {
        a1 = b4[lane + 32];
        float4 v1 = h4[(long long)d * NV4 + lane + 32];
        a1.x += sl * v1.x; a1.y += sl * v1.y; a1.z += sl * v1.z; a1.w += sl * v1.w;
    }

    int j = g_rowoff[d];
    int end = g_rowoff[d + 1];
    for (; j < end; j++) {
        int s = g_csr_src[j];
        float nrm = g_csr_nrm[j];
        const float4* hr = h4 + (long long)s * NV4;
        float4 v = hr[lane];
        a0.x += nrm * v.x; a0.y += nrm * v.y; a0.z += nrm * v.z; a0.w += nrm * v.w;
        if constexpr (C == 256) {
            float4 w = hr[lane + 32];
            a1.x += nrm * w.x; a1.y += nrm * w.y; a1.z += nrm * w.z; a1.w += nrm * w.w;
        }
    }

    a0.x = fmaxf(a0.x, 0.f); a0.y = fmaxf(a0.y, 0.f);
    a0.z = fmaxf(a0.z, 0.f); a0.w = fmaxf(a0.w, 0.f);
    ((float4*)out)[(long long)d * NV4 + lane] = a0;
    if constexpr (C == 256) {
        a1.x = fmaxf(a1.x, 0.f); a1.y = fmaxf(a1.y, 0.f);
        a1.z = fmaxf(a1.z, 0.f); a1.w = fmaxf(a1.w, 0.f);
        ((float4*)out)[(long long)d * NV4 + lane + 32] = a1;
    }
}

// ---------------- attention pooling ----------------
__global__ void k_logits(const float* __restrict__ emb,
                         const float* __restrict__ Wa,
                         const float* __restrict__ ba) {
    __shared__ float smax[8];
    int lane = threadIdx.x & 31;
    int wid = threadIdx.x >> 5;
    int d = blockIdx.x * 8 + wid;   // N divisible by 8 (50000 = 6250*8)

    const float4* e4 = (const float4*)(emb + (long long)d * C2);
    const float4* w4 = (const float4*)Wa;
    float s = 0.f;
#pragma unroll
    for (int j = 0; j < 2; j++) {
        float4 e = e4[lane + 32 * j];
        float4 w = w4[lane + 32 * j];
        s += e.x * w.x + e.y * w.y + e.z * w.z + e.w * w.w;
    }
#pragma unroll
    for (int o = 16; o > 0; o >>= 1) s += __shfl_xor_sync(0xffffffffu, s, o);
    float l = s + ba[0];
    if (lane == 0) { g_logits[d] = l; smax[wid] = l; }
    __syncthreads();
    if (threadIdx.x == 0) {
        float m = smax[0];
#pragma unroll
        for (int i = 1; i < 8; i++) m = fmaxf(m, smax[i]);
        atomicMax(&g_maxkey, enc_f(m));
    }
}

__global__ void k_exp() {
    __shared__ float sh[256];
    int t = threadIdx.x;
    int i = blockIdx.x * 256 + t;
    float m = dec_f(g_maxkey);
    float p = 0.f;
    if (i < N_NODES) {
        p = expf(g_logits[i] - m);
        g_pw[i] = p;
    }
    sh[t] = p;
    __syncthreads();
    for (int off = 128; off > 0; off >>= 1) {
        if (t < off) sh[t] += sh[t + off];
        __syncthreads();
    }
    if (t == 0) atomicAdd(&g_sumexp, sh[0]);
}

__global__ void k_zero_gout(float* gout) { gout[threadIdx.x] = 0.f; }

__global__ void k_graph(const float* __restrict__ emb, float* __restrict__ gout) {
    int c = threadIdx.x; // 256 channels
    float acc = 0.f;
    for (int i = blockIdx.x; i < N_NODES; i += gridDim.x)
        acc += emb[(long long)i * C2 + c] * g_pw[i];
    atomicAdd(&gout[c], acc);
}

__global__ void k_scale(float* gout) {
    gout[threadIdx.x] *= (1.0f / g_sumexp);
}

// ---------------- launcher ----------------
extern "C" void kernel_launch(void* const* d_in, const int* in_sizes, int n_in,
                              void* d_out, int out_size) {
    const float* x  = (const float*)d_in[0];
    const void*  ei = d_in[1];
    const float* W1 = (const float*)d_in[2];
    const float* b1 = (const float*)d_in[3];
    const float* W2 = (const float*)d_in[4];
    const float* b2 = (const float*)d_in[5];
    const float* Wa = (const float*)d_in[6];
    const float* ba = (const float*)d_in[7];

    float* emb  = (float*)d_out;                              // (N, 256)
    float* gout = (float*)d_out + (long long)N_NODES * C2;    // (1, 256)

    k_sniff<<<1, 1>>>(ei);
    k_init<<<NB_N, 256>>>();
    k_count<<<NB_E, 256>>>(ei);
    k_dinv<<<NB_N, 256>>>();
    k_scan1<<<NB_N, 256>>>();
    k_scan2<<<1, 256>>>();
    k_scan3<<<NB_N, 256>>>();
    k_cursor<<<NB_N, 256>>>();
    k_scatter<<<NB_E, 256>>>(ei);

    k_gemm<C1><<<dim3(296, 2), 256>>>(x, W1, g_h1);
    k_agg<C1><<<(N_NODES + 7) / 8, 256>>>(g_h1, b1, g_agg1);
    k_gemm<C2><<<dim3(148, 4), 256>>>(g_agg1, W2, g_h2);
    k_agg<C2><<<(N_NODES + 7) / 8, 256>>>(g_h2, b2, emb);

    k_logits<<<N_NODES / 8, 256>>>(emb, Wa, ba);
    k_exp<<<NB_N, 256>>>();
    k_zero_gout<<<1, 256>>>(gout);
    k_graph<<<512, 256>>>(emb, gout);
    k_scale<<<1, 256>>>(gout);
}